// round 11
// baseline (speedup 1.0000x reference)
#include <cuda_runtime.h>

#define TT 100
#define BB 32768

// ---- frozen arithmetic (R5/R8, passing, rel_err 5.53e-4) ----
// Per neuron: NEON 4-lane dot as 2x f32x2 chains over float4 groups,
// pairwise reduce (l0+l1)+(l2+l3), scalar fma tail, bias after,
// LIF: fmaf(0.9,m,cur) - reset (reset from PREVIOUS mem), spike = nm>1.

typedef unsigned long long u64;

__device__ __forceinline__ u64 fma2(u64 a, u64 b, u64 c) {
    u64 d;
    asm("fma.rn.f32x2 %0, %1, %2, %3;" : "=l"(d) : "l"(a), "l"(b), "l"(c));
    return d;
}

__device__ __forceinline__ float reduce2x2(u64 a01, u64 a23) {
    float l0, l1, l2, l3;
    asm("mov.b64 {%0,%1}, %2;" : "=f"(l0), "=f"(l1) : "l"(a01));
    asm("mov.b64 {%0,%1}, %2;" : "=f"(l2), "=f"(l3) : "l"(a23));
    return __fadd_rn(__fadd_rn(l0, l1), __fadd_rn(l2, l3));
}

// weight row stride 36 floats (144B: 16B-aligned rows)
#define WS 36

__global__ __launch_bounds__(32) void snn_kernel(
    const float* __restrict__ x,
    const float* __restrict__ w_s1, const float* __restrict__ b_s1,
    const float* __restrict__ w_s2, const float* __restrict__ b_s2,
    const float* __restrict__ w_c1, const float* __restrict__ b_c1,
    const float* __restrict__ w_co, const float* __restrict__ b_co,
    const float* __restrict__ w_ro, const float* __restrict__ b_ro,
    float* __restrict__ out)
{
    // ALL vector-accessed shared arrays explicitly 16B-aligned.
    __shared__ __align__(16) float s_ws1[28 * WS];
    __shared__ __align__(16) float s_ws2[14 * WS];
    __shared__ __align__(16) float s_wc1[8 * WS];
    __shared__ __align__(16) float s_wco[3 * WS];
    __shared__ __align__(16) float s_wro[WS];
    __shared__ float s_bs1[28], s_bs2[14], s_bc1[8], s_bco[3], s_bro[1];
    // transposed spike buffers: [element][neuron], 16B-aligned base + row strides
    __shared__ __align__(16) float s_spk1T[8][36];   // 28 used, 144B rows
    __shared__ __align__(16) float s_spk2T[8][20];   // 14 used, 80B rows
    __shared__ __align__(16) float s_spkc1T[8][12];  // 8 used, 48B rows

    const int tid = threadIdx.x;
    // ---- load weights (padded rows) ----
    for (int i = tid; i < 28 * WS; i += 32) { int r = i / WS, c = i % WS; s_ws1[i] = (c < 32) ? w_s1[r * 32 + c] : 0.0f; }
    for (int i = tid; i < 14 * WS; i += 32) { int r = i / WS, c = i % WS; s_ws2[i] = (c < 28) ? w_s2[r * 28 + c] : 0.0f; }
    for (int i = tid; i < 8 * WS;  i += 32) { int r = i / WS, c = i % WS; s_wc1[i] = (c < 14) ? w_c1[r * 14 + c] : 0.0f; }
    for (int i = tid; i < 3 * WS;  i += 32) { int r = i / WS, c = i % WS; s_wco[i] = (c < 8)  ? w_co[r * 8 + c]  : 0.0f; }
    for (int i = tid; i < WS;      i += 32) s_wro[i] = (i < 14) ? w_ro[i] : 0.0f;
    for (int i = tid; i < 28; i += 32) s_bs1[i] = b_s1[i];
    for (int i = tid; i < 14; i += 32) s_bs2[i] = b_s2[i];
    for (int i = tid; i < 8;  i += 32) s_bc1[i] = b_c1[i];
    for (int i = tid; i < 3;  i += 32) s_bco[i] = b_co[i];
    if (tid == 0) s_bro[0] = b_ro[0];
    __syncthreads();

    const int eid = tid >> 2;        // 0..7  element within block
    const int p   = tid & 3;         // 0..3  neuron-partition
    const int b   = blockIdx.x * 8 + eid;

    // membranes owned per thread (neurons j = p + 4k)
    float m1[7], m2[4], mc1[2];
    #pragma unroll
    for (int k = 0; k < 7; k++) m1[k] = 0.0f;
    #pragma unroll
    for (int k = 0; k < 4; k++) m2[k] = 0.0f;
    mc1[0] = 0.0f; mc1[1] = 0.0f;
    float mco_v = 0.0f;   // valid for p<3 (neuron p)
    float mro_v = 0.0f;   // valid for p==3

    float* o_mco   = out;                          // (T,B,3)
    float* o_spkc1 = out + (size_t)TT * BB * 3;    // (T,B,8)
    float* o_mro   = out + (size_t)TT * BB * 11;   // (T,B,1)
    float* o_spk1  = out + (size_t)TT * BB * 12;   // (T,B,28)
    float* o_spk2  = out + (size_t)TT * BB * 40;   // (T,B,14)

    #pragma unroll 1
    for (int t = 0; t < TT; t++) {
        const size_t base = (size_t)t * BB + b;

        // ---- load x_t[b][0:32] (4 threads/element read same row; L1 multicast) ----
        ulonglong2 xv[8];
        {
            const ulonglong2* xt = (const ulonglong2*)(x + base * 32);
            #pragma unroll
            for (int i = 0; i < 8; i++) xv[i] = xt[i];
        }

        // ---- layer s1: 32 -> 28, thread owns j = p + 4k, k=0..6 ----
        #pragma unroll
        for (int k = 0; k < 7; k++) {
            const int j = p + 4 * k;
            const ulonglong2* wr = (const ulonglong2*)&s_ws1[j * WS];
            u64 a01 = 0ull, a23 = 0ull;
            #pragma unroll
            for (int i = 0; i < 8; i++) {
                ulonglong2 w = wr[i];
                a01 = fma2(w.x, xv[i].x, a01);
                a23 = fma2(w.y, xv[i].y, a23);
            }
            float cur = __fadd_rn(reduce2x2(a01, a23), s_bs1[j]);
            float m   = m1[k];
            float rst = (m > 1.0f) ? 1.0f : 0.0f;
            float nm  = __fadd_rn(fmaf(0.9f, m, cur), -rst);
            m1[k] = nm;
            s_spk1T[eid][j] = (nm > 1.0f) ? 1.0f : 0.0f;
        }
        __syncwarp();

        // gather all 28 spk1 (7x LDS.128)
        float spk1r[28];
        {
            const float4* src = (const float4*)&s_spk1T[eid][0];
            float4* dst = (float4*)spk1r;
            #pragma unroll
            for (int i = 0; i < 7; i++) dst[i] = src[i];
        }

        // ---- layer s2: 28 -> 14, j = p + 4k (k=0..3, j<14) ----
        #pragma unroll
        for (int k = 0; k < 4; k++) {
            const int j = p + 4 * k;
            if (j < 14) {
                const ulonglong2* wr = (const ulonglong2*)&s_ws2[j * WS];
                const ulonglong2* vr = (const ulonglong2*)spk1r;
                u64 a01 = 0ull, a23 = 0ull;
                #pragma unroll
                for (int i = 0; i < 7; i++) {
                    ulonglong2 w = wr[i];
                    ulonglong2 v = vr[i];
                    a01 = fma2(w.x, v.x, a01);
                    a23 = fma2(w.y, v.y, a23);
                }
                float cur = __fadd_rn(reduce2x2(a01, a23), s_bs2[j]);
                float m   = m2[k];
                float rst = (m > 1.0f) ? 1.0f : 0.0f;
                float nm  = __fadd_rn(fmaf(0.9f, m, cur), -rst);
                m2[k] = nm;
                s_spk2T[eid][j] = (nm > 1.0f) ? 1.0f : 0.0f;
            }
        }
        __syncwarp();

        // gather 14 spk2 (3x LDS.128 + LDS.64)
        float spk2r[14];
        {
            const float4* src = (const float4*)&s_spk2T[eid][0];
            float4* dst = (float4*)spk2r;
            #pragma unroll
            for (int i = 0; i < 3; i++) dst[i] = src[i];
            ((float2*)spk2r)[6] = ((const float2*)&s_spk2T[eid][0])[6];
        }

        // ---- layer c1: 14 -> 8, j = p + 4k (k=0..1); 3 vec groups + tail 12,13 ----
        #pragma unroll
        for (int k = 0; k < 2; k++) {
            const int j = p + 4 * k;
            const ulonglong2* wr = (const ulonglong2*)&s_wc1[j * WS];
            const ulonglong2* vr = (const ulonglong2*)spk2r;
            u64 a01 = 0ull, a23 = 0ull;
            #pragma unroll
            for (int i = 0; i < 3; i++) {
                ulonglong2 w = wr[i];
                ulonglong2 v = vr[i];
                a01 = fma2(w.x, v.x, a01);
                a23 = fma2(w.y, v.y, a23);
            }
            float s = reduce2x2(a01, a23);
            s = fmaf(s_wc1[j * WS + 12], spk2r[12], s);
            s = fmaf(s_wc1[j * WS + 13], spk2r[13], s);
            float cur = __fadd_rn(s, s_bc1[j]);
            float m   = mc1[k];
            float rst = (m > 1.0f) ? 1.0f : 0.0f;
            float nm  = __fadd_rn(fmaf(0.9f, m, cur), -rst);
            mc1[k] = nm;
            s_spkc1T[eid][j] = (nm > 1.0f) ? 1.0f : 0.0f;
        }
        __syncwarp();

        // gather 8 spkc1 (2x LDS.128)
        float spkc1r[8];
        {
            const float4* src = (const float4*)&s_spkc1T[eid][0];
            float4* dst = (float4*)spkc1r;
            dst[0] = src[0];
            dst[1] = src[1];
        }

        // ---- layer co: 8 -> 3, thread p<3 owns neuron p ----
        if (p < 3) {
            const ulonglong2* wr = (const ulonglong2*)&s_wco[p * WS];
            const ulonglong2* vr = (const ulonglong2*)spkc1r;
            u64 a01 = 0ull, a23 = 0ull;
            #pragma unroll
            for (int i = 0; i < 2; i++) {
                ulonglong2 w = wr[i];
                ulonglong2 v = vr[i];
                a01 = fma2(w.x, v.x, a01);
                a23 = fma2(w.y, v.y, a23);
            }
            float cur = __fadd_rn(reduce2x2(a01, a23), s_bco[p]);
            float rst = (mco_v > 1.0f) ? 1.0f : 0.0f;
            mco_v = __fadd_rn(fmaf(0.9f, mco_v, cur), -rst);
            o_mco[base * 3 + p] = mco_v;
        }

        // ---- layer ro: 14 -> 1, thread p==3 ----
        if (p == 3) {
            const ulonglong2* wr = (const ulonglong2*)s_wro;
            const ulonglong2* vr = (const ulonglong2*)spk2r;
            u64 a01 = 0ull, a23 = 0ull;
            #pragma unroll
            for (int i = 0; i < 3; i++) {
                ulonglong2 w = wr[i];
                ulonglong2 v = vr[i];
                a01 = fma2(w.x, v.x, a01);
                a23 = fma2(w.y, v.y, a23);
            }
            float s = reduce2x2(a01, a23);
            s = fmaf(s_wro[12], spk2r[12], s);
            s = fmaf(s_wro[13], spk2r[13], s);
            float cur = __fadd_rn(s, s_bro[0]);
            float rst = (mro_v > 1.0f) ? 1.0f : 0.0f;
            mro_v = __fadd_rn(fmaf(0.9f, mro_v, cur), -rst);
            o_mro[base] = mro_v;
        }

        // ---- spike stores, spread across the 4 threads ----
        {
            // spk1: (T,B,28) -> byte offset base*112 (16B-aligned): float4 OK
            float4* r1 = (float4*)(o_spk1 + base * 28);
            const float4* s1v = (const float4*)spk1r;
            if (p == 0) { r1[0] = s1v[0]; r1[1] = s1v[1]; }
            else if (p == 1) { r1[2] = s1v[2]; r1[3] = s1v[3]; }
            else if (p == 2) { r1[4] = s1v[4]; r1[5] = s1v[5]; }
            else { r1[6] = s1v[6]; }

            // spk2: (T,B,14) -> byte offset base*56 (8B only): float2 ONLY
            {
                float2* r2 = (float2*)(o_spk2 + base * 14);
                const float2* s2v = (const float2*)spk2r;
                if (p == 0)      { r2[0] = s2v[0]; r2[1] = s2v[1]; }
                else if (p == 1) { r2[2] = s2v[2]; r2[3] = s2v[3]; }
                else if (p == 2) { r2[4] = s2v[4]; r2[5] = s2v[5]; }
                else             { r2[6] = s2v[6]; }
            }

            // spkc1: (T,B,8) -> byte offset base*32 (16B-aligned): float4 OK
            float4* rc = (float4*)(o_spkc1 + base * 8);
            const float4* scv = (const float4*)spkc1r;
            if (p == 0) rc[0] = scv[0];
            else if (p == 1) rc[1] = scv[1];
        }
    }
}

extern "C" void kernel_launch(void* const* d_in, const int* in_sizes, int n_in,
                              void* d_out, int out_size) {
    snn_kernel<<<BB / 8, 32>>>(
        (const float*)d_in[0],
        (const float*)d_in[1],  (const float*)d_in[2],
        (const float*)d_in[3],  (const float*)d_in[4],
        (const float*)d_in[5],  (const float*)d_in[6],
        (const float*)d_in[7],  (const float*)d_in[8],
        (const float*)d_in[9],  (const float*)d_in[10],
        (float*)d_out);
}

// round 12
// speedup vs baseline: 1.4093x; 1.4093x over previous
#include <cuda_runtime.h>

#define TT 100
#define BB 32768

// ---- frozen arithmetic (R5/R8, passing, rel_err 5.5296e-4) ----
// Per neuron: NEON 4-lane dot as 2x f32x2 chains over float4 groups,
// pairwise reduce (l0+l1)+(l2+l3), scalar fma tail, bias after,
// LIF: fmaf(0.9,m,cur) - reset (reset from PREVIOUS mem), spike = nm>1.

typedef unsigned long long u64;

__device__ __forceinline__ u64 fma2(u64 a, u64 b, u64 c) {
    u64 d;
    asm("fma.rn.f32x2 %0, %1, %2, %3;" : "=l"(d) : "l"(a), "l"(b), "l"(c));
    return d;
}

__device__ __forceinline__ float reduce2x2(u64 a01, u64 a23) {
    float l0, l1, l2, l3;
    asm("mov.b64 {%0,%1}, %2;" : "=f"(l0), "=f"(l1) : "l"(a01));
    asm("mov.b64 {%0,%1}, %2;" : "=f"(l2), "=f"(l3) : "l"(a23));
    return __fadd_rn(__fadd_rn(l0, l1), __fadd_rn(l2, l3));
}

__global__ __launch_bounds__(32) void snn_kernel(
    const float* __restrict__ x,
    const float* __restrict__ w_s1, const float* __restrict__ b_s1,
    const float* __restrict__ w_s2, const float* __restrict__ b_s2,
    const float* __restrict__ w_c1, const float* __restrict__ b_c1,
    const float* __restrict__ w_co, const float* __restrict__ b_co,
    const float* __restrict__ w_ro, const float* __restrict__ b_ro,
    float* __restrict__ out)
{
    __shared__ __align__(16) float s_ws1[28 * 32];
    __shared__ __align__(16) float s_ws2[14 * 28];
    __shared__ __align__(16) float s_wc1[8 * 16];
    __shared__ __align__(16) float s_wco[3 * 8];
    __shared__ __align__(16) float s_wro[16];
    __shared__ float s_bs1[28], s_bs2[14], s_bc1[8], s_bco[3], s_bro[1];
    __shared__ __align__(16) float s_m1[28][32];
    __shared__ __align__(16) float s_m2[14][32];
    __shared__ __align__(16) float s_mc1[8][32];
    __shared__ __align__(16) float s_spk1[28][32];
    __shared__ __align__(16) float s_spk2[14][32];
    __shared__ __align__(16) float s_spkc1[8][32];

    const int tid = threadIdx.x;
    for (int i = tid; i < 28 * 32; i += 32) s_ws1[i] = w_s1[i];
    for (int i = tid; i < 14 * 28; i += 32) s_ws2[i] = w_s2[i];
    for (int i = tid; i < 8 * 16;  i += 32) s_wc1[i] = (i % 16 < 14) ? w_c1[(i / 16) * 14 + (i % 16)] : 0.0f;
    for (int i = tid; i < 3 * 8;   i += 32) s_wco[i] = w_co[i];
    if (tid < 16) s_wro[tid] = (tid < 14) ? w_ro[tid] : 0.0f;
    for (int i = tid; i < 28; i += 32) s_bs1[i] = b_s1[i];
    for (int i = tid; i < 14; i += 32) s_bs2[i] = b_s2[i];
    for (int i = tid; i < 8;  i += 32) s_bc1[i] = b_c1[i];
    for (int i = tid; i < 3;  i += 32) s_bco[i] = b_co[i];
    if (tid == 0) s_bro[0] = b_ro[0];

    for (int j = 0; j < 28; j++) s_m1[j][tid] = 0.0f;
    for (int j = 0; j < 14; j++) s_m2[j][tid] = 0.0f;
    for (int j = 0; j < 8;  j++) s_mc1[j][tid] = 0.0f;
    float mco0 = 0.0f, mco1 = 0.0f, mco2 = 0.0f, mro = 0.0f;
    __syncthreads();

    const int b = blockIdx.x * 32 + tid;

    float* o_mco   = out;                          // (T,B,3)
    float* o_spkc1 = out + (size_t)TT * BB * 3;    // (T,B,8)
    float* o_mro   = out + (size_t)TT * BB * 11;   // (T,B,1)
    float* o_spk1  = out + (size_t)TT * BB * 12;   // (T,B,28)
    float* o_spk2  = out + (size_t)TT * BB * 40;   // (T,B,14)

    // prefetch x for t=0 as packed 16B groups: .x=(f0,f1) .y=(f2,f3)
    ulonglong2 xv[8];
    {
        const ulonglong2* xt = (const ulonglong2*)(x + ((size_t)0 * BB + b) * 32);
        #pragma unroll
        for (int i = 0; i < 8; i++) xv[i] = xt[i];
    }

    #pragma unroll 1
    for (int t = 0; t < TT; t++) {
        const size_t base = (size_t)t * BB + b;

        // ---- prefetch x for t+1 (clamped; overlaps this step's compute) ----
        ulonglong2 xn[8];
        {
            int tn = (t + 1 < TT) ? (t + 1) : (TT - 1);
            const ulonglong2* xt2 = (const ulonglong2*)(x + ((size_t)tn * BB + b) * 32);
            #pragma unroll
            for (int i = 0; i < 8; i++) xn[i] = xt2[i];
        }

        // ---- layer s1: 32 -> 28 (7 independent chains in flight) ----
        #pragma unroll 7
        for (int j = 0; j < 28; j++) {
            const ulonglong2* wr = (const ulonglong2*)&s_ws1[j * 32];
            u64 a01 = 0ull, a23 = 0ull;
            #pragma unroll
            for (int i = 0; i < 8; i++) {
                ulonglong2 w = wr[i];
                a01 = fma2(w.x, xv[i].x, a01);
                a23 = fma2(w.y, xv[i].y, a23);
            }
            float cur = __fadd_rn(reduce2x2(a01, a23), s_bs1[j]);
            float m   = s_m1[j][tid];
            float rst = (m > 1.0f) ? 1.0f : 0.0f;      // reset uses PREVIOUS mem
            float nm  = __fadd_rn(fmaf(0.9f, m, cur), -rst);
            s_m1[j][tid]   = nm;
            s_spk1[j][tid] = (nm > 1.0f) ? 1.0f : 0.0f;
        }

        // reload spk1 (constant-indexed)
        float spk1r[28];
        #pragma unroll
        for (int i = 0; i < 28; i++) spk1r[i] = s_spk1[i][tid];

        // ---- layer s2: 28 -> 14 (7 chains in flight) ----
        #pragma unroll 7
        for (int j = 0; j < 14; j++) {
            const ulonglong2* wr = (const ulonglong2*)&s_ws2[j * 28];
            const ulonglong2* vr = (const ulonglong2*)spk1r;
            u64 a01 = 0ull, a23 = 0ull;
            #pragma unroll
            for (int i = 0; i < 7; i++) {
                ulonglong2 w = wr[i];
                ulonglong2 v = vr[i];
                a01 = fma2(w.x, v.x, a01);
                a23 = fma2(w.y, v.y, a23);
            }
            float cur = __fadd_rn(reduce2x2(a01, a23), s_bs2[j]);
            float m   = s_m2[j][tid];
            float rst = (m > 1.0f) ? 1.0f : 0.0f;
            float nm  = __fadd_rn(fmaf(0.9f, m, cur), -rst);
            s_m2[j][tid]   = nm;
            s_spk2[j][tid] = (nm > 1.0f) ? 1.0f : 0.0f;
        }

        float spk2r[14];
        #pragma unroll
        for (int i = 0; i < 14; i++) spk2r[i] = s_spk2[i][tid];

        // ---- layer c1: 14 -> 8, fully unrolled (3 vec groups + tail 12,13) ----
        #pragma unroll
        for (int j = 0; j < 8; j++) {
            const ulonglong2* wr = (const ulonglong2*)&s_wc1[j * 16];
            const ulonglong2* vr = (const ulonglong2*)spk2r;
            u64 a01 = 0ull, a23 = 0ull;
            #pragma unroll
            for (int i = 0; i < 3; i++) {
                ulonglong2 w = wr[i];
                ulonglong2 v = vr[i];
                a01 = fma2(w.x, v.x, a01);
                a23 = fma2(w.y, v.y, a23);
            }
            float s = reduce2x2(a01, a23);
            s = fmaf(s_wc1[j * 16 + 12], spk2r[12], s);
            s = fmaf(s_wc1[j * 16 + 13], spk2r[13], s);
            float cur = __fadd_rn(s, s_bc1[j]);
            float m   = s_mc1[j][tid];
            float rst = (m > 1.0f) ? 1.0f : 0.0f;
            float nm  = __fadd_rn(fmaf(0.9f, m, cur), -rst);
            s_mc1[j][tid]   = nm;
            s_spkc1[j][tid] = (nm > 1.0f) ? 1.0f : 0.0f;
        }

        float spkc1r[8];
        #pragma unroll
        for (int i = 0; i < 8; i++) spkc1r[i] = s_spkc1[i][tid];

        // ---- layer co: 8 -> 3 (mem in regs) ----
        {
            const ulonglong2* vr = (const ulonglong2*)spkc1r;
            #pragma unroll
            for (int j = 0; j < 3; j++) {
                const ulonglong2* wr = (const ulonglong2*)&s_wco[j * 8];
                u64 a01 = 0ull, a23 = 0ull;
                #pragma unroll
                for (int i = 0; i < 2; i++) {
                    ulonglong2 w = wr[i];
                    ulonglong2 v = vr[i];
                    a01 = fma2(w.x, v.x, a01);
                    a23 = fma2(w.y, v.y, a23);
                }
                float cur = __fadd_rn(reduce2x2(a01, a23), s_bco[j]);
                float m   = (j == 0) ? mco0 : (j == 1) ? mco1 : mco2;
                float rst = (m > 1.0f) ? 1.0f : 0.0f;
                float nm  = __fadd_rn(fmaf(0.9f, m, cur), -rst);
                if (j == 0) mco0 = nm; else if (j == 1) mco1 = nm; else mco2 = nm;
            }
        }

        // ---- layer ro: 14 -> 1 (mem in reg) ----
        {
            const ulonglong2* wr = (const ulonglong2*)s_wro;
            const ulonglong2* vr = (const ulonglong2*)spk2r;
            u64 a01 = 0ull, a23 = 0ull;
            #pragma unroll
            for (int i = 0; i < 3; i++) {
                ulonglong2 w = wr[i];
                ulonglong2 v = vr[i];
                a01 = fma2(w.x, v.x, a01);
                a23 = fma2(w.y, v.y, a23);
            }
            float s = reduce2x2(a01, a23);
            s = fmaf(s_wro[12], spk2r[12], s);
            s = fmaf(s_wro[13], spk2r[13], s);
            float cur = __fadd_rn(s, s_bro[0]);
            float rst = (mro > 1.0f) ? 1.0f : 0.0f;
            mro = __fadd_rn(fmaf(0.9f, mro, cur), -rst);
        }

        // ---- stores (vectorized, coalesced) ----
        {
            float* p = o_mco + base * 3;
            p[0] = mco0; p[1] = mco1; p[2] = mco2;
        }
        {
            float4* q = (float4*)(o_spkc1 + base * 8);
            q[0] = make_float4(spkc1r[0], spkc1r[1], spkc1r[2], spkc1r[3]);
            q[1] = make_float4(spkc1r[4], spkc1r[5], spkc1r[6], spkc1r[7]);
        }
        o_mro[base] = mro;
        {
            float4* r = (float4*)(o_spk1 + base * 28);
            #pragma unroll
            for (int j = 0; j < 7; j++)
                r[j] = make_float4(spk1r[4 * j], spk1r[4 * j + 1],
                                   spk1r[4 * j + 2], spk1r[4 * j + 3]);
        }
        {
            float2* s2 = (float2*)(o_spk2 + base * 14);
            #pragma unroll
            for (int j = 0; j < 7; j++)
                s2[j] = make_float2(spk2r[2 * j], spk2r[2 * j + 1]);
        }

        // rotate prefetched x
        #pragma unroll
        for (int i = 0; i < 8; i++) xv[i] = xn[i];
    }
}

extern "C" void kernel_launch(void* const* d_in, const int* in_sizes, int n_in,
                              void* d_out, int out_size) {
    snn_kernel<<<BB / 32, 32>>>(
        (const float*)d_in[0],
        (const float*)d_in[1],  (const float*)d_in[2],
        (const float*)d_in[3],  (const float*)d_in[4],
        (const float*)d_in[5],  (const float*)d_in[6],
        (const float*)d_in[7],  (const float*)d_in[8],
        (const float*)d_in[9],  (const float*)d_in[10],
        (float*)d_out);
}

// round 13
// speedup vs baseline: 1.6132x; 1.1447x over previous
#include <cuda_runtime.h>

#define TT 100
#define BB 32768

// ---- frozen arithmetic (R5/R8, passing, rel_err 5.5296e-4) ----
// Per neuron: NEON 4-lane dot as 2x f32x2 chains over float4 groups,
// pairwise reduce (l0+l1)+(l2+l3), scalar fma tail, bias after,
// LIF: fmaf(0.9,m,cur) - reset (reset from PREVIOUS mem), spike = nm>1.

typedef unsigned long long u64;

__device__ __forceinline__ u64 fma2(u64 a, u64 b, u64 c) {
    u64 d;
    asm("fma.rn.f32x2 %0, %1, %2, %3;" : "=l"(d) : "l"(a), "l"(b), "l"(c));
    return d;
}

__device__ __forceinline__ float reduce2x2(u64 a01, u64 a23) {
    float l0, l1, l2, l3;
    asm("mov.b64 {%0,%1}, %2;" : "=f"(l0), "=f"(l1) : "l"(a01));
    asm("mov.b64 {%0,%1}, %2;" : "=f"(l2), "=f"(l3) : "l"(a23));
    return __fadd_rn(__fadd_rn(l0, l1), __fadd_rn(l2, l3));
}

__global__ __launch_bounds__(32) void snn_kernel(
    const float* __restrict__ x,
    const float* __restrict__ w_s1, const float* __restrict__ b_s1,
    const float* __restrict__ w_s2, const float* __restrict__ b_s2,
    const float* __restrict__ w_c1, const float* __restrict__ b_c1,
    const float* __restrict__ w_co, const float* __restrict__ b_co,
    const float* __restrict__ w_ro, const float* __restrict__ b_ro,
    float* __restrict__ out)
{
    __shared__ __align__(16) float s_ws1[28 * 32];
    __shared__ __align__(16) float s_ws2[14 * 28];
    __shared__ __align__(16) float s_wc1[8 * 16];
    __shared__ __align__(16) float s_wco[3 * 8];
    __shared__ __align__(16) float s_wro[16];
    __shared__ float s_bs1[28], s_bs2[14], s_bc1[8], s_bco[3], s_bro[1];
    // membranes paired: [neuron_pair][tid] = (m_{2k}, m_{2k+1})
    __shared__ __align__(8) float2 s_m1p[14][32];
    __shared__ __align__(8) float2 s_m2p[7][32];
    __shared__ __align__(8) float2 s_mc1p[4][32];

    const int tid = threadIdx.x;
    for (int i = tid; i < 28 * 32; i += 32) s_ws1[i] = w_s1[i];
    for (int i = tid; i < 14 * 28; i += 32) s_ws2[i] = w_s2[i];
    for (int i = tid; i < 8 * 16;  i += 32) s_wc1[i] = (i % 16 < 14) ? w_c1[(i / 16) * 14 + (i % 16)] : 0.0f;
    for (int i = tid; i < 3 * 8;   i += 32) s_wco[i] = w_co[i];
    if (tid < 16) s_wro[tid] = (tid < 14) ? w_ro[tid] : 0.0f;
    for (int i = tid; i < 28; i += 32) s_bs1[i] = b_s1[i];
    for (int i = tid; i < 14; i += 32) s_bs2[i] = b_s2[i];
    for (int i = tid; i < 8;  i += 32) s_bc1[i] = b_c1[i];
    for (int i = tid; i < 3;  i += 32) s_bco[i] = b_co[i];
    if (tid == 0) s_bro[0] = b_ro[0];

    for (int k = 0; k < 14; k++) s_m1p[k][tid] = make_float2(0.0f, 0.0f);
    for (int k = 0; k < 7;  k++) s_m2p[k][tid] = make_float2(0.0f, 0.0f);
    for (int k = 0; k < 4;  k++) s_mc1p[k][tid] = make_float2(0.0f, 0.0f);
    float mco0 = 0.0f, mco1 = 0.0f, mco2 = 0.0f, mro = 0.0f;
    __syncthreads();

    const int b = blockIdx.x * 32 + tid;

    float* o_mco   = out;                          // (T,B,3)
    float* o_spkc1 = out + (size_t)TT * BB * 3;    // (T,B,8)
    float* o_mro   = out + (size_t)TT * BB * 11;   // (T,B,1)
    float* o_spk1  = out + (size_t)TT * BB * 12;   // (T,B,28)
    float* o_spk2  = out + (size_t)TT * BB * 40;   // (T,B,14)

    // prefetch x for t=0 as packed 16B groups: .x=(f0,f1) .y=(f2,f3)
    ulonglong2 xv[8];
    {
        const ulonglong2* xt = (const ulonglong2*)(x + ((size_t)0 * BB + b) * 32);
        #pragma unroll
        for (int i = 0; i < 8; i++) xv[i] = xt[i];
    }

    #pragma unroll 1
    for (int t = 0; t < TT; t++) {
        const size_t base = (size_t)t * BB + b;

        // ---- prefetch x for t+1 (clamped; overlaps this step's compute) ----
        ulonglong2 xn[8];
        {
            int tn = (t + 1 < TT) ? (t + 1) : (TT - 1);
            const ulonglong2* xt2 = (const ulonglong2*)(x + ((size_t)tn * BB + b) * 32);
            #pragma unroll
            for (int i = 0; i < 8; i++) xn[i] = xt2[i];
        }

        // ---- layer s1: 32 -> 28, neuron pairs ----
        unsigned bits1 = 0;
        #pragma unroll 7
        for (int k = 0; k < 14; k++) {
            const int j0 = 2 * k, j1 = 2 * k + 1;
            const ulonglong2* wr0 = (const ulonglong2*)&s_ws1[j0 * 32];
            const ulonglong2* wr1 = (const ulonglong2*)&s_ws1[j1 * 32];
            u64 a01 = 0ull, a23 = 0ull, b01 = 0ull, b23 = 0ull;
            #pragma unroll
            for (int i = 0; i < 8; i++) {
                ulonglong2 w0 = wr0[i];
                ulonglong2 w1 = wr1[i];
                a01 = fma2(w0.x, xv[i].x, a01);
                a23 = fma2(w0.y, xv[i].y, a23);
                b01 = fma2(w1.x, xv[i].x, b01);
                b23 = fma2(w1.y, xv[i].y, b23);
            }
            float cur0 = __fadd_rn(reduce2x2(a01, a23), s_bs1[j0]);
            float cur1 = __fadd_rn(reduce2x2(b01, b23), s_bs1[j1]);
            float2 mp  = s_m1p[k][tid];
            float rst0 = (mp.x > 1.0f) ? 1.0f : 0.0f;   // reset uses PREVIOUS mem
            float rst1 = (mp.y > 1.0f) ? 1.0f : 0.0f;
            float nm0  = __fadd_rn(fmaf(0.9f, mp.x, cur0), -rst0);
            float nm1  = __fadd_rn(fmaf(0.9f, mp.y, cur1), -rst1);
            s_m1p[k][tid] = make_float2(nm0, nm1);
            bits1 |= ((nm0 > 1.0f) ? 1u : 0u) << j0;
            bits1 |= ((nm1 > 1.0f) ? 1u : 0u) << j1;
        }

        // unpack spk1 to register array (exact 0.0f/1.0f)
        float spk1r[28];
        #pragma unroll
        for (int i = 0; i < 28; i++) spk1r[i] = ((bits1 >> i) & 1u) ? 1.0f : 0.0f;

        // ---- layer s2: 28 -> 14, neuron pairs ----
        unsigned bits2 = 0;
        #pragma unroll 7
        for (int k = 0; k < 7; k++) {
            const int j0 = 2 * k, j1 = 2 * k + 1;
            const ulonglong2* wr0 = (const ulonglong2*)&s_ws2[j0 * 28];
            const ulonglong2* wr1 = (const ulonglong2*)&s_ws2[j1 * 28];
            const ulonglong2* vr  = (const ulonglong2*)spk1r;
            u64 a01 = 0ull, a23 = 0ull, b01 = 0ull, b23 = 0ull;
            #pragma unroll
            for (int i = 0; i < 7; i++) {
                ulonglong2 w0 = wr0[i];
                ulonglong2 w1 = wr1[i];
                ulonglong2 v  = vr[i];
                a01 = fma2(w0.x, v.x, a01);
                a23 = fma2(w0.y, v.y, a23);
                b01 = fma2(w1.x, v.x, b01);
                b23 = fma2(w1.y, v.y, b23);
            }
            float cur0 = __fadd_rn(reduce2x2(a01, a23), s_bs2[j0]);
            float cur1 = __fadd_rn(reduce2x2(b01, b23), s_bs2[j1]);
            float2 mp  = s_m2p[k][tid];
            float rst0 = (mp.x > 1.0f) ? 1.0f : 0.0f;
            float rst1 = (mp.y > 1.0f) ? 1.0f : 0.0f;
            float nm0  = __fadd_rn(fmaf(0.9f, mp.x, cur0), -rst0);
            float nm1  = __fadd_rn(fmaf(0.9f, mp.y, cur1), -rst1);
            s_m2p[k][tid] = make_float2(nm0, nm1);
            bits2 |= ((nm0 > 1.0f) ? 1u : 0u) << j0;
            bits2 |= ((nm1 > 1.0f) ? 1u : 0u) << j1;
        }

        float spk2r[14];
        #pragma unroll
        for (int i = 0; i < 14; i++) spk2r[i] = ((bits2 >> i) & 1u) ? 1.0f : 0.0f;

        // ---- layer c1: 14 -> 8, neuron pairs (3 vec groups + tail 12,13) ----
        unsigned bitsc = 0;
        #pragma unroll
        for (int k = 0; k < 4; k++) {
            const int j0 = 2 * k, j1 = 2 * k + 1;
            const ulonglong2* wr0 = (const ulonglong2*)&s_wc1[j0 * 16];
            const ulonglong2* wr1 = (const ulonglong2*)&s_wc1[j1 * 16];
            const ulonglong2* vr  = (const ulonglong2*)spk2r;
            u64 a01 = 0ull, a23 = 0ull, b01 = 0ull, b23 = 0ull;
            #pragma unroll
            for (int i = 0; i < 3; i++) {
                ulonglong2 w0 = wr0[i];
                ulonglong2 w1 = wr1[i];
                ulonglong2 v  = vr[i];
                a01 = fma2(w0.x, v.x, a01);
                a23 = fma2(w0.y, v.y, a23);
                b01 = fma2(w1.x, v.x, b01);
                b23 = fma2(w1.y, v.y, b23);
            }
            float s0 = reduce2x2(a01, a23);
            float s1v = reduce2x2(b01, b23);
            s0  = fmaf(s_wc1[j0 * 16 + 12], spk2r[12], s0);
            s0  = fmaf(s_wc1[j0 * 16 + 13], spk2r[13], s0);
            s1v = fmaf(s_wc1[j1 * 16 + 12], spk2r[12], s1v);
            s1v = fmaf(s_wc1[j1 * 16 + 13], spk2r[13], s1v);
            float cur0 = __fadd_rn(s0,  s_bc1[j0]);
            float cur1 = __fadd_rn(s1v, s_bc1[j1]);
            float2 mp  = s_mc1p[k][tid];
            float rst0 = (mp.x > 1.0f) ? 1.0f : 0.0f;
            float rst1 = (mp.y > 1.0f) ? 1.0f : 0.0f;
            float nm0  = __fadd_rn(fmaf(0.9f, mp.x, cur0), -rst0);
            float nm1  = __fadd_rn(fmaf(0.9f, mp.y, cur1), -rst1);
            s_mc1p[k][tid] = make_float2(nm0, nm1);
            bitsc |= ((nm0 > 1.0f) ? 1u : 0u) << j0;
            bitsc |= ((nm1 > 1.0f) ? 1u : 0u) << j1;
        }

        float spkc1r[8];
        #pragma unroll
        for (int i = 0; i < 8; i++) spkc1r[i] = ((bitsc >> i) & 1u) ? 1.0f : 0.0f;

        // ---- layer co: 8 -> 3 (mem in regs) ----
        {
            const ulonglong2* vr = (const ulonglong2*)spkc1r;
            #pragma unroll
            for (int j = 0; j < 3; j++) {
                const ulonglong2* wr = (const ulonglong2*)&s_wco[j * 8];
                u64 a01 = 0ull, a23 = 0ull;
                #pragma unroll
                for (int i = 0; i < 2; i++) {
                    ulonglong2 w = wr[i];
                    ulonglong2 v = vr[i];
                    a01 = fma2(w.x, v.x, a01);
                    a23 = fma2(w.y, v.y, a23);
                }
                float cur = __fadd_rn(reduce2x2(a01, a23), s_bco[j]);
                float m   = (j == 0) ? mco0 : (j == 1) ? mco1 : mco2;
                float rst = (m > 1.0f) ? 1.0f : 0.0f;
                float nm  = __fadd_rn(fmaf(0.9f, m, cur), -rst);
                if (j == 0) mco0 = nm; else if (j == 1) mco1 = nm; else mco2 = nm;
            }
        }

        // ---- layer ro: 14 -> 1 (mem in reg) ----
        {
            const ulonglong2* wr = (const ulonglong2*)s_wro;
            const ulonglong2* vr = (const ulonglong2*)spk2r;
            u64 a01 = 0ull, a23 = 0ull;
            #pragma unroll
            for (int i = 0; i < 3; i++) {
                ulonglong2 w = wr[i];
                ulonglong2 v = vr[i];
                a01 = fma2(w.x, v.x, a01);
                a23 = fma2(w.y, v.y, a23);
            }
            float s = reduce2x2(a01, a23);
            s = fmaf(s_wro[12], spk2r[12], s);
            s = fmaf(s_wro[13], spk2r[13], s);
            float cur = __fadd_rn(s, s_bro[0]);
            float rst = (mro > 1.0f) ? 1.0f : 0.0f;
            mro = __fadd_rn(fmaf(0.9f, mro, cur), -rst);
        }

        // ---- stores (vectorized, coalesced) ----
        {
            float* p = o_mco + base * 3;
            p[0] = mco0; p[1] = mco1; p[2] = mco2;
        }
        {
            float4* q = (float4*)(o_spkc1 + base * 8);
            q[0] = make_float4(spkc1r[0], spkc1r[1], spkc1r[2], spkc1r[3]);
            q[1] = make_float4(spkc1r[4], spkc1r[5], spkc1r[6], spkc1r[7]);
        }
        o_mro[base] = mro;
        {
            float4* r = (float4*)(o_spk1 + base * 28);
            #pragma unroll
            for (int j = 0; j < 7; j++)
                r[j] = make_float4(spk1r[4 * j], spk1r[4 * j + 1],
                                   spk1r[4 * j + 2], spk1r[4 * j + 3]);
        }
        {
            float2* s2 = (float2*)(o_spk2 + base * 14);
            #pragma unroll
            for (int j = 0; j < 7; j++)
                s2[j] = make_float2(spk2r[2 * j], spk2r[2 * j + 1]);
        }

        // rotate prefetched x
        #pragma unroll
        for (int i = 0; i < 8; i++) xv[i] = xn[i];
    }
}

extern "C" void kernel_launch(void* const* d_in, const int* in_sizes, int n_in,
                              void* d_out, int out_size) {
    snn_kernel<<<BB / 32, 32>>>(
        (const float*)d_in[0],
        (const float*)d_in[1],  (const float*)d_in[2],
        (const float*)d_in[3],  (const float*)d_in[4],
        (const float*)d_in[5],  (const float*)d_in[6],
        (const float*)d_in[7],  (const float*)d_in[8],
        (const float*)d_in[9],  (const float*)d_in[10],
        (float*)d_out);
}